// round 1
// baseline (speedup 1.0000x reference)
#include <cuda_runtime.h>

// ---------------------------------------------------------------------------
// FullyConnectedVQCs: 4-qubit circuits, theta-invariant unitaries precomputed.
//   Stage A: 4 circuits (theta[0][blk]),  angles H[4b+q]   -> H[4b+q]
//   Stage B: 4 circuits (theta[3][j]),    angles H[4q+j]   -> H[4j+q]
//   Stage C: 4 circuits (theta[4][j]),    same wiring
//   Stage D: 4 circuits (theta[1][j]),    angles H[4q+j]   -> H4[j]   (1 out)
//   Stage E: 1 circuit  (theta[2][0]),    angles H4[q]     -> out     (1 out)
// Qubit 0 = MSB of the 4-bit amplitude index.
// ---------------------------------------------------------------------------

#define NC 17

__device__ __align__(16) float2 g_W[NC][16][16];   // [circuit][row k][col j]

__device__ __forceinline__ int circ_slice(int c) {
    if (c < 4)  return 0 * 4 + c;          // stage A -> theta[0]
    if (c < 8)  return 3 * 4 + (c - 4);    // stage B -> theta[3]
    if (c < 12) return 4 * 4 + (c - 8);    // stage C -> theta[4]
    if (c < 16) return 1 * 4 + (c - 12);   // stage D -> theta[1]
    return 2 * 4;                          // stage E -> theta[2][0]
}

// Build the 16x16 unitary of one circuit's SEL block. One block per circuit,
// one thread per basis column. All gate loops fully unrolled -> registers.
__global__ void build_W(const float* __restrict__ theta) {
    const int c   = blockIdx.x;
    const int col = threadIdx.x;           // 0..15
    const float* w = theta + circ_slice(c) * 48;   // [l][q][p], 4*4*3

    float sr[16], si[16];
#pragma unroll
    for (int i = 0; i < 16; i++) { sr[i] = (i == col) ? 1.f : 0.f; si[i] = 0.f; }

#pragma unroll
    for (int l = 0; l < 4; l++) {
#pragma unroll
        for (int q = 0; q < 4; q++) {
            float phi = w[(l * 4 + q) * 3 + 0];
            float th  = w[(l * 4 + q) * 3 + 1];
            float om  = w[(l * 4 + q) * 3 + 2];
            float ch, sh, ca, sa, cb, sb;
            sincosf(0.5f * th, &sh, &ch);
            sincosf(0.5f * (phi + om), &sa, &ca);
            sincosf(0.5f * (phi - om), &sb, &cb);
            // qml.Rot = RZ(om) RY(th) RZ(phi)
            const float u00r =  ca * ch, u00i = -sa * ch;
            const float u01r = -cb * sh, u01i = -sb * sh;
            const float u10r =  cb * sh, u10i = -sb * sh;
            const float u11r =  ca * ch, u11i =  sa * ch;
            const int mask = 8 >> q;
#pragma unroll
            for (int k = 0; k < 16; k++) {
                if (k & mask) continue;
                const int k1 = k | mask;
                float ar = sr[k],  ai = si[k];
                float br = sr[k1], bi = si[k1];
                sr[k]  = u00r * ar - u00i * ai + u01r * br - u01i * bi;
                si[k]  = u00r * ai + u00i * ar + u01r * bi + u01i * br;
                sr[k1] = u10r * ar - u10i * ai + u11r * br - u11i * bi;
                si[k1] = u10r * ai + u10i * ar + u11r * bi + u11i * br;
            }
        }
        const int r = (l % 3) + 1;         // SEL ranges 1,2,3,1
#pragma unroll
        for (int q = 0; q < 4; q++) {
            const int cm = 8 >> q;
            const int tm = 8 >> ((q + r) & 3);
#pragma unroll
            for (int k = 0; k < 16; k++) {
                if ((k & cm) && !(k & tm)) {
                    const int k1 = k | tm;
                    float tr = sr[k], ti = si[k];
                    sr[k] = sr[k1]; si[k] = si[k1];
                    sr[k1] = tr;    si[k1] = ti;
                }
            }
        }
    }
#pragma unroll
    for (int k = 0; k < 16; k++)
        g_W[c][k][col] = make_float2(sr[k], si[k]);
}

// ---------------------------------------------------------------------------
// f32x2 packed-FMA helpers
// ---------------------------------------------------------------------------
__device__ __forceinline__ unsigned long long pk2(float lo, float hi) {
    unsigned long long r;
    asm("mov.b64 %0, {%1, %2};" : "=l"(r) : "f"(lo), "f"(hi));
    return r;
}
__device__ __forceinline__ void unpk2(unsigned long long v, float& lo, float& hi) {
    asm("mov.b64 {%0, %1}, %2;" : "=f"(lo), "=f"(hi) : "l"(v));
}
__device__ __forceinline__ unsigned long long ffma2(unsigned long long a,
                                                    unsigned long long b,
                                                    unsigned long long c) {
    unsigned long long d;
#if defined(__CUDA_ARCH__) && (__CUDA_ARCH__ >= 1000)
    asm("fma.rn.f32x2 %0, %1, %2, %3;" : "=l"(d) : "l"(a), "l"(b), "l"(c));
#else
    float ar, ai, br, bi, cr, ci;
    unpk2(a, ar, ai); unpk2(b, br, bi); unpk2(c, cr, ci);
    d = pk2(fmaf(ar, br, cr), fmaf(ai, bi, ci));
#endif
    return d;
}

// Signed accumulate: e += (bit ? -p : p) via sign-bit XOR (LOP3 + FADD).
__device__ __forceinline__ float sgnadd(float e, float p, unsigned sbit) {
    return e + __uint_as_float(__float_as_uint(p) ^ sbit);
}

// One circuit: embed 4 RY angles into product state psi (real), y = W psi
// (complex GEMV via f32x2), expvals from signed sums of |y_k|^2.
template <int NOUT>
__device__ __forceinline__ void run_circuit(const float4* __restrict__ W,
                                            float a0, float a1, float a2, float a3,
                                            float* out) {
    float s0, c0, s1, c1, s2, c2, s3, c3;
    __sincosf(0.5f * a0, &s0, &c0);
    __sincosf(0.5f * a1, &s1, &c1);
    __sincosf(0.5f * a2, &s2, &c2);
    __sincosf(0.5f * a3, &s3, &c3);
    const float u[4] = { c0 * c1, c0 * s1, s0 * c1, s0 * s1 };
    const float v[4] = { c2 * c3, c2 * s3, s2 * c3, s2 * s3 };
    unsigned long long pp[16];
#pragma unroll
    for (int i = 0; i < 4; i++)
#pragma unroll
        for (int j = 0; j < 4; j++) {
            const float p = u[i] * v[j];
            pp[i * 4 + j] = pk2(p, p);
        }

    float e0 = 0.f, e1 = 0.f, e2 = 0.f, e3 = 0.f;
#pragma unroll 4
    for (int k = 0; k < 16; k++) {
        unsigned long long acc0 = 0ull, acc1 = 0ull;
#pragma unroll
        for (int jj = 0; jj < 8; jj++) {
            const float4 w = W[k * 8 + jj];               // 2 complex entries
            acc0 = ffma2(pk2(w.x, w.y), pp[2 * jj + 0], acc0);
            acc1 = ffma2(pk2(w.z, w.w), pp[2 * jj + 1], acc1);
        }
        float r0, i0, r1, i1;
        unpk2(acc0, r0, i0); unpk2(acc1, r1, i1);
        const float yr = r0 + r1, yi = i0 + i1;
        const float p = yr * yr + yi * yi;
        e0 = sgnadd(e0, p, ((unsigned)(k & 8)) << 28);    // qubit 0 = MSB
        if (NOUT > 1) {
            e1 = sgnadd(e1, p, ((unsigned)(k & 4)) << 29);
            e2 = sgnadd(e2, p, ((unsigned)(k & 2)) << 30);
            e3 = sgnadd(e3, p, ((unsigned)(k & 1)) << 31);
        }
    }
    out[0] = e0;
    if (NOUT > 1) { out[1] = e1; out[2] = e2; out[3] = e3; }
}

__global__ __launch_bounds__(128)
void vqc_main(const float* __restrict__ x, float* __restrict__ out, int B) {
    __shared__ float4 sW[NC * 128];       // 17 * 16*16 complex = 34 KB
    {
        const float4* g = reinterpret_cast<const float4*>(g_W);
        for (int i = threadIdx.x; i < NC * 128; i += blockDim.x) sW[i] = g[i];
    }
    __syncthreads();

    const int b = blockIdx.x * blockDim.x + threadIdx.x;
    if (b >= B) return;

    float H[16], Hn[16], H4[4];
    H[0] = 0.f;
#pragma unroll
    for (int i = 0; i < 13; i++) H[1 + i] = x[b * 13 + i];
    H[14] = 0.f; H[15] = 0.f;

    // Stage A: contiguous blocks
#pragma unroll
    for (int blk = 0; blk < 4; blk++)
        run_circuit<4>(sW + (0 + blk) * 128,
                       H[4 * blk], H[4 * blk + 1], H[4 * blk + 2], H[4 * blk + 3],
                       &Hn[4 * blk]);
    // Stage B: transposed wiring, Hn -> H
#pragma unroll
    for (int j = 0; j < 4; j++)
        run_circuit<4>(sW + (4 + j) * 128,
                       Hn[j], Hn[4 + j], Hn[8 + j], Hn[12 + j], &H[4 * j]);
    // Stage C: H -> Hn
#pragma unroll
    for (int j = 0; j < 4; j++)
        run_circuit<4>(sW + (8 + j) * 128,
                       H[j], H[4 + j], H[8 + j], H[12 + j], &Hn[4 * j]);
    // Stage D: 16 -> 4 (one expval each)
#pragma unroll
    for (int j = 0; j < 4; j++)
        run_circuit<1>(sW + (12 + j) * 128,
                       Hn[j], Hn[4 + j], Hn[8 + j], Hn[12 + j], &H4[j]);
    // Stage E: 4 -> 1
    float o;
    run_circuit<1>(sW + 16 * 128, H4[0], H4[1], H4[2], H4[3], &o);

    out[b] = o * (float)(3.141592653589793 - 1.1920928955078125e-7);
}

extern "C" void kernel_launch(void* const* d_in, const int* in_sizes, int n_in,
                              void* d_out, int out_size) {
    const float* x     = (const float*)d_in[0];
    const float* theta = (const float*)d_in[1];
    if (n_in >= 2 && in_sizes[0] < in_sizes[1]) {   // robustness to input order
        x     = (const float*)d_in[1];
        theta = (const float*)d_in[0];
    }
    float* out = (float*)d_out;
    const int B = out_size;

    build_W<<<17, 16>>>(theta);
    const int tpb = 128;
    vqc_main<<<(B + tpb - 1) / tpb, tpb>>>(x, out, B);
}